// round 6
// baseline (speedup 1.0000x reference)
#include <cuda_runtime.h>
#include <math.h>

namespace {
constexpr int NSEQ = 512;
constexpr int LRES = 1024;
constexpr int NT   = 512;
constexpr float LN_EPS = 1e-5f;

typedef unsigned long long ull;

struct __align__(16) Smem {
    float xg[64 * NSEQ];       // 128 KB: X transposed+swizzled, then G in place
    float wc[64][80];          // 20 KB: cols 0-63 Wg, 64-71 Wk, 72-79 Wv
    float wo[64 * 64];         // 16 KB (scaled by ovec before pass B)
    float kbuf[NSEQ][8];       // 16 KB
    float vT[8 * NSEQ];        // 16 KB (v transposed)
    float scores[8 * NSEQ];    // 16 KB
    float lnw[64], lnb[64], bgv[64], bov[64], xsum[64], qvec[64], ovec[64];
    float xpart[16][64];       // 4 KB
};

__device__ __forceinline__ int swz(int c) { return ((c >> 3) ^ c) & 7; }
__device__ __forceinline__ void ffma2(ull& d_, ull a, ull b) {
    asm("fma.rn.f32x2 %0, %1, %2, %0;" : "+l"(d_) : "l"(a), "l"(b));
}
__device__ __forceinline__ ull splat2(float x) {
    ull r; asm("mov.b64 %0, {%1, %1};" : "=l"(r) : "f"(x)); return r;
}
__device__ __forceinline__ ull add2(ull a, ull b) {
    ull r; asm("add.rn.f32x2 %0, %1, %2;" : "=l"(r) : "l"(a), "l"(b)); return r;
}
__device__ __forceinline__ void unpack2(ull u, float& lo, float& hi) {
    asm("mov.b64 {%0, %1}, %2;" : "=f"(lo), "=f"(hi) : "l"(u));
}
__device__ __forceinline__ float sigmoid_fast(float v) {
    return __fdividef(1.f, 1.f + __expf(-v));
}
} // namespace

__global__ void __launch_bounds__(NT, 1)
msa_col_attn_v5(const float* __restrict__ msa,
                const float* __restrict__ g_lnw, const float* __restrict__ g_lnb,
                const float* __restrict__ g_wq,  const float* __restrict__ g_wk,
                const float* __restrict__ g_wv,  const float* __restrict__ g_wg,
                const float* __restrict__ g_bg,  const float* __restrict__ g_wo,
                const float* __restrict__ g_bo,  float* __restrict__ out)
{
    extern __shared__ float smem_f[];
    Smem* s = reinterpret_cast<Smem*>(smem_f);
    const int tid  = threadIdx.x;
    const int l    = blockIdx.x;
    const int lane = tid & 31;
    const int wid  = tid >> 5;

    // ---------------- preamble: weights to SMEM ----------------
    #pragma unroll
    for (int i = 0; i < 8; ++i) {
        int idx = tid + i * NT;
        s->wc[idx >> 6][idx & 63] = g_wg[idx];
    }
    {   // Wk/Wv are exactly 512 elements each: ONE pass of 512 threads
        int d = tid >> 3, j = tid & 7;
        s->wc[d][64 + j] = g_wk[tid];
        s->wc[d][72 + j] = g_wv[tid];
    }
    #pragma unroll
    for (int i = 0; i < 2; ++i) {
        int idx = tid + i * NT;
        ((float4*)s->wo)[idx] = ((const float4*)g_wo)[idx];
    }
    if (tid < 64) {
        s->lnw[tid] = g_lnw[tid];
        s->lnb[tid] = g_lnb[tid];
        s->bgv[tid] = g_bg[tid];
        s->bov[tid] = g_bo[tid];
    }
    // wq in registers: thread (dg=tid>>6, c=tid&63) holds wq[8dg+i][c]
    float wqr[8];
    {
        int dg = tid >> 6, c = tid & 63;
        #pragma unroll
        for (int i = 0; i < 8; ++i) wqr[i] = g_wq[(8 * dg + i) * 64 + c];
    }
    __syncthreads();

    // ---------------- LayerNorm: full 512x64 -> xg (transposed, swizzled) ----------------
    // warp covers 2 rows per iteration; 16 lanes span one full 256B row
    {
        const int lq4 = lane & 15;   // 16B chunk of the row
        const int lh  = lane >> 4;   // which of the warp's 2 rows
        const size_t step = (size_t)32 * LRES * 64;
        const float* base = msa + ((size_t)(wid * 2 + lh) * LRES + l) * 64 + lq4 * 4;
        float xacc0 = 0.f, xacc1 = 0.f, xacc2 = 0.f, xacc3 = 0.f;
        float4 cur = *reinterpret_cast<const float4*>(base);
        #pragma unroll 1
        for (int it = 0; it < 16; ++it) {
            float4 nxt = make_float4(0.f, 0.f, 0.f, 0.f);
            if (it < 15)
                nxt = *reinterpret_cast<const float4*>(base + (size_t)(it + 1) * step);
            float sm = (cur.x + cur.y) + (cur.z + cur.w);
            float sq = fmaf(cur.x, cur.x, fmaf(cur.y, cur.y,
                       fmaf(cur.z, cur.z, cur.w * cur.w)));
            #pragma unroll
            for (int off = 1; off < 16; off <<= 1) {
                sm += __shfl_xor_sync(0xffffffffu, sm, off);
                sq += __shfl_xor_sync(0xffffffffu, sq, off);
            }
            float mu   = sm * (1.f / 64.f);
            float var  = sq * (1.f / 64.f) - mu * mu;
            float rstd = rsqrtf(var + LN_EPS);
            float mrs  = -mu * rstd;
            int row = it * 32 + wid * 2 + lh;
            int rb = row >> 2, r0 = row & 3;
            int c0 = 4 * lq4;
            float v0 = fmaf(fmaf(cur.x, rstd, mrs), s->lnw[c0 + 0], s->lnb[c0 + 0]);
            float v1 = fmaf(fmaf(cur.y, rstd, mrs), s->lnw[c0 + 1], s->lnb[c0 + 1]);
            float v2 = fmaf(fmaf(cur.z, rstd, mrs), s->lnw[c0 + 2], s->lnb[c0 + 2]);
            float v3 = fmaf(fmaf(cur.w, rstd, mrs), s->lnw[c0 + 3], s->lnb[c0 + 3]);
            s->xg[(c0 + 0) * NSEQ + 4 * (rb ^ swz(c0 + 0)) + r0] = v0;
            s->xg[(c0 + 1) * NSEQ + 4 * (rb ^ swz(c0 + 1)) + r0] = v1;
            s->xg[(c0 + 2) * NSEQ + 4 * (rb ^ swz(c0 + 2)) + r0] = v2;
            s->xg[(c0 + 3) * NSEQ + 4 * (rb ^ swz(c0 + 3)) + r0] = v3;
            xacc0 += v0; xacc1 += v1; xacc2 += v2; xacc3 += v3;
            cur = nxt;
        }
        xacc0 += __shfl_xor_sync(0xffffffffu, xacc0, 16);
        xacc1 += __shfl_xor_sync(0xffffffffu, xacc1, 16);
        xacc2 += __shfl_xor_sync(0xffffffffu, xacc2, 16);
        xacc3 += __shfl_xor_sync(0xffffffffu, xacc3, 16);
        if (lane < 16) {
            s->xpart[wid][4 * lq4 + 0] = xacc0;
            s->xpart[wid][4 * lq4 + 1] = xacc1;
            s->xpart[wid][4 * lq4 + 2] = xacc2;
            s->xpart[wid][4 * lq4 + 3] = xacc3;
        }
    }
    __syncthreads();

    // xsum (consumed after the next barrier)
    if (tid < 64) {
        float t = 0.f;
        #pragma unroll
        for (int w = 0; w < 16; ++w) t += s->xpart[w][tid];
        s->xsum[tid] = t;
    }

    // ---------------- pass A: gate GEMM (8 rows x 8 cols per thread) ----------------
    const int rg = tid >> 3;   // rows 8rg..8rg+7
    const int cg = tid & 7;    // gate cols 8cg..8cg+7
    ull ga[8][4];
    #pragma unroll
    for (int r = 0; r < 8; ++r)
        #pragma unroll
        for (int p = 0; p < 4; ++p) ga[r][p] = 0;

    #pragma unroll 4
    for (int d = 0; d < 64; ++d) {
        const float* xp = &s->xg[d * NSEQ];
        float4 xa = *reinterpret_cast<const float4*>(xp + 4 * ((2 * rg) ^ swz(d)));
        float4 xb = *reinterpret_cast<const float4*>(xp + 4 * ((2 * rg + 1) ^ swz(d)));
        ulonglong2 w0 = *reinterpret_cast<const ulonglong2*>(&s->wc[d][8 * cg]);
        ulonglong2 w1 = *reinterpret_cast<const ulonglong2*>(&s->wc[d][8 * cg + 4]);
        ull t;
        t = splat2(xa.x); ffma2(ga[0][0],t,w0.x); ffma2(ga[0][1],t,w0.y); ffma2(ga[0][2],t,w1.x); ffma2(ga[0][3],t,w1.y);
        t = splat2(xa.y); ffma2(ga[1][0],t,w0.x); ffma2(ga[1][1],t,w0.y); ffma2(ga[1][2],t,w1.x); ffma2(ga[1][3],t,w1.y);
        t = splat2(xa.z); ffma2(ga[2][0],t,w0.x); ffma2(ga[2][1],t,w0.y); ffma2(ga[2][2],t,w1.x); ffma2(ga[2][3],t,w1.y);
        t = splat2(xa.w); ffma2(ga[3][0],t,w0.x); ffma2(ga[3][1],t,w0.y); ffma2(ga[3][2],t,w1.x); ffma2(ga[3][3],t,w1.y);
        t = splat2(xb.x); ffma2(ga[4][0],t,w0.x); ffma2(ga[4][1],t,w0.y); ffma2(ga[4][2],t,w1.x); ffma2(ga[4][3],t,w1.y);
        t = splat2(xb.y); ffma2(ga[5][0],t,w0.x); ffma2(ga[5][1],t,w0.y); ffma2(ga[5][2],t,w1.x); ffma2(ga[5][3],t,w1.y);
        t = splat2(xb.z); ffma2(ga[6][0],t,w0.x); ffma2(ga[6][1],t,w0.y); ffma2(ga[6][2],t,w1.x); ffma2(ga[6][3],t,w1.y);
        t = splat2(xb.w); ffma2(ga[7][0],t,w0.x); ffma2(ga[7][1],t,w0.y); ffma2(ga[7][2],t,w1.x); ffma2(ga[7][3],t,w1.y);
    }

    // ---------------- pass A: kv GEMM (8 rows x 2 cols, row-pair packed) ----------------
    // cg<4 -> k cols {2cg, 2cg+1}; cg>=4 -> v cols {2cg-8, 2cg-7}
    ull ka[4][2];
    #pragma unroll
    for (int p = 0; p < 4; ++p) { ka[p][0] = 0; ka[p][1] = 0; }
    #pragma unroll 8
    for (int d = 0; d < 64; ++d) {
        const float* xp = &s->xg[d * NSEQ];
        ulonglong2 xa = *reinterpret_cast<const ulonglong2*>(xp + 4 * ((2 * rg) ^ swz(d)));
        ulonglong2 xb = *reinterpret_cast<const ulonglong2*>(xp + 4 * ((2 * rg + 1) ^ swz(d)));
        float2 wk = *reinterpret_cast<const float2*>(&s->wc[d][64 + 2 * cg]);
        ull w0 = splat2(wk.x), w1 = splat2(wk.y);
        ffma2(ka[0][0], xa.x, w0); ffma2(ka[0][1], xa.x, w1);
        ffma2(ka[1][0], xa.y, w0); ffma2(ka[1][1], xa.y, w1);
        ffma2(ka[2][0], xb.x, w0); ffma2(ka[2][1], xb.x, w1);
        ffma2(ka[3][0], xb.y, w0); ffma2(ka[3][1], xb.y, w1);
    }
    __syncthreads();   // all xg reads done; safe to overwrite with G

    // gate epilogue: G = sigmoid(P + bg) -> xg (same transposed+swizzled layout)
    #pragma unroll
    for (int c = 0; c < 8; ++c) {
        int col = 8 * cg + c;
        float bgc = s->bgv[col];
        float g[8];
        #pragma unroll
        for (int r = 0; r < 8; ++r) {
            float lo, hi;
            unpack2(ga[r][c >> 1], lo, hi);
            float v = (c & 1) ? hi : lo;
            g[r] = sigmoid_fast(v + bgc);
        }
        float* dst = &s->xg[col * NSEQ];
        *reinterpret_cast<float4*>(dst + 4 * ((2 * rg) ^ swz(col)))     = make_float4(g[0], g[1], g[2], g[3]);
        *reinterpret_cast<float4*>(dst + 4 * ((2 * rg + 1) ^ swz(col))) = make_float4(g[4], g[5], g[6], g[7]);
    }
    // kv epilogue
    if (cg < 4) {
        #pragma unroll
        for (int p = 0; p < 4; ++p) {
            float a0, a1, b0, b1;
            unpack2(ka[p][0], a0, a1);   // col 2cg, rows 2p,2p+1
            unpack2(ka[p][1], b0, b1);   // col 2cg+1
            s->kbuf[8 * rg + 2 * p    ][2 * cg]     = a0;
            s->kbuf[8 * rg + 2 * p    ][2 * cg + 1] = b0;
            s->kbuf[8 * rg + 2 * p + 1][2 * cg]     = a1;
            s->kbuf[8 * rg + 2 * p + 1][2 * cg + 1] = b1;
        }
    } else {
        int c0 = 2 * cg - 8;
        float a[8], b[8];
        #pragma unroll
        for (int p = 0; p < 4; ++p) {
            unpack2(ka[p][0], a[2 * p], a[2 * p + 1]);
            unpack2(ka[p][1], b[2 * p], b[2 * p + 1]);
        }
        *reinterpret_cast<float4*>(&s->vT[c0 * NSEQ + 8 * rg])           = make_float4(a[0], a[1], a[2], a[3]);
        *reinterpret_cast<float4*>(&s->vT[c0 * NSEQ + 8 * rg + 4])       = make_float4(a[4], a[5], a[6], a[7]);
        *reinterpret_cast<float4*>(&s->vT[(c0 + 1) * NSEQ + 8 * rg])     = make_float4(b[0], b[1], b[2], b[3]);
        *reinterpret_cast<float4*>(&s->vT[(c0 + 1) * NSEQ + 8 * rg + 4]) = make_float4(b[4], b[5], b[6], b[7]);
    }
    // qvec partials (xsum was written before the previous barrier)
    {
        int dg = tid >> 6, c = tid & 63;
        float p = 0.f;
        #pragma unroll
        for (int i = 0; i < 8; ++i) p = fmaf(s->xsum[8 * dg + i], wqr[i], p);
        s->xpart[dg][c] = p;
    }
    __syncthreads();

    if (tid < 64) {
        float q = 0.f;
        #pragma unroll
        for (int dg = 0; dg < 8; ++dg) q += s->xpart[dg][tid];
        s->qvec[tid] = q * (float)(0.35355339059327373 / 512.0); // (1/sqrt(8))/N
    }
    __syncthreads();

    // ---------------- scores[h][n] ----------------
    {
        float4 k0 = *reinterpret_cast<const float4*>(&s->kbuf[tid][0]);
        float4 k1 = *reinterpret_cast<const float4*>(&s->kbuf[tid][4]);
        #pragma unroll
        for (int h = 0; h < 8; ++h) {
            const float* qf = &s->qvec[h * 8];
            float sc = qf[0]*k0.x + qf[1]*k0.y + qf[2]*k0.z + qf[3]*k0.w
                     + qf[4]*k1.x + qf[5]*k1.y + qf[6]*k1.z + qf[7]*k1.w;
            s->scores[h * NSEQ + tid] = sc;
        }
    }
    __syncthreads();

    // ---------------- softmax + o = attn @ v (one warp per head) ----------------
    if (wid < 8) {
        float sv[16];
        float m = -1e30f;
        #pragma unroll
        for (int k = 0; k < 16; ++k) {
            sv[k] = s->scores[wid * NSEQ + lane + 32 * k];
            m = fmaxf(m, sv[k]);
        }
        #pragma unroll
        for (int off = 16; off > 0; off >>= 1)
            m = fmaxf(m, __shfl_xor_sync(0xffffffffu, m, off));
        float ssum = 0.f;
        float acc[8];
        #pragma unroll
        for (int d = 0; d < 8; ++d) acc[d] = 0.f;
        #pragma unroll
        for (int k = 0; k < 16; ++k) {
            float e = __expf(sv[k] - m);
            ssum += e;
            int n = lane + 32 * k;
            #pragma unroll
            for (int d = 0; d < 8; ++d)
                acc[d] = fmaf(e, s->vT[d * NSEQ + n], acc[d]);
        }
        #pragma unroll
        for (int off = 16; off > 0; off >>= 1) {
            ssum += __shfl_xor_sync(0xffffffffu, ssum, off);
            #pragma unroll
            for (int d = 0; d < 8; ++d)
                acc[d] += __shfl_xor_sync(0xffffffffu, acc[d], off);
        }
        if (lane == 0) {
            float inv = 1.f / ssum;
            #pragma unroll
            for (int d = 0; d < 8; ++d) s->ovec[wid * 8 + d] = acc[d] * inv;
        }
    }
    __syncthreads();

    // fold ovec into Wo rows
    #pragma unroll
    for (int i = 0; i < 8; ++i) {
        int idx = tid + i * NT;
        s->wo[idx] *= s->ovec[idx >> 6];
    }
    __syncthreads();

    // ---------------- pass B: out = G @ Wo' + bo ----------------
    {
        ull acc[8][4];
        #pragma unroll
        for (int i = 0; i < 8; ++i)
            #pragma unroll
            for (int p = 0; p < 4; ++p) acc[i][p] = 0;

        #pragma unroll 4
        for (int d = 0; d < 64; ++d) {
            const float* gp = &s->xg[d * NSEQ];
            float4 xa = *reinterpret_cast<const float4*>(gp + 4 * ((2 * rg) ^ swz(d)));
            float4 xb = *reinterpret_cast<const float4*>(gp + 4 * ((2 * rg + 1) ^ swz(d)));
            ulonglong2 wA = *reinterpret_cast<const ulonglong2*>(&s->wo[d * 64 + 8 * cg]);
            ulonglong2 wB = *reinterpret_cast<const ulonglong2*>(&s->wo[d * 64 + 8 * cg + 4]);
            ull t;
            t = splat2(xa.x); ffma2(acc[0][0],t,wA.x); ffma2(acc[0][1],t,wA.y); ffma2(acc[0][2],t,wB.x); ffma2(acc[0][3],t,wB.y);
            t = splat2(xa.y); ffma2(acc[1][0],t,wA.x); ffma2(acc[1][1],t,wA.y); ffma2(acc[1][2],t,wB.x); ffma2(acc[1][3],t,wB.y);
            t = splat2(xa.z); ffma2(acc[2][0],t,wA.x); ffma2(acc[2][1],t,wA.y); ffma2(acc[2][2],t,wB.x); ffma2(acc[2][3],t,wB.y);
            t = splat2(xa.w); ffma2(acc[3][0],t,wA.x); ffma2(acc[3][1],t,wA.y); ffma2(acc[3][2],t,wB.x); ffma2(acc[3][3],t,wB.y);
            t = splat2(xb.x); ffma2(acc[4][0],t,wA.x); ffma2(acc[4][1],t,wA.y); ffma2(acc[4][2],t,wB.x); ffma2(acc[4][3],t,wB.y);
            t = splat2(xb.y); ffma2(acc[5][0],t,wA.x); ffma2(acc[5][1],t,wA.y); ffma2(acc[5][2],t,wB.x); ffma2(acc[5][3],t,wB.y);
            t = splat2(xb.z); ffma2(acc[6][0],t,wA.x); ffma2(acc[6][1],t,wA.y); ffma2(acc[6][2],t,wB.x); ffma2(acc[6][3],t,wB.y);
            t = splat2(xb.w); ffma2(acc[7][0],t,wA.x); ffma2(acc[7][1],t,wA.y); ffma2(acc[7][2],t,wB.x); ffma2(acc[7][3],t,wB.y);
        }

        const ulonglong2 boA = *reinterpret_cast<const ulonglong2*>(&s->bov[8 * cg]);
        const ulonglong2 boB = *reinterpret_cast<const ulonglong2*>(&s->bov[8 * cg + 4]);
        #pragma unroll
        for (int i = 0; i < 8; ++i) {
            size_t row = (size_t)(8 * rg + i);
            float* op = out + (row * LRES + l) * 64 + 8 * cg;
            ulonglong2 v0, v1;
            v0.x = add2(acc[i][0], boA.x); v0.y = add2(acc[i][1], boA.y);
            v1.x = add2(acc[i][2], boB.x); v1.y = add2(acc[i][3], boB.y);
            *reinterpret_cast<ulonglong2*>(op)     = v0;
            *reinterpret_cast<ulonglong2*>(op + 4) = v1;
        }
    }
}

extern "C" void kernel_launch(void* const* d_in, const int* in_sizes, int n_in,
                              void* d_out, int out_size) {
    const float* msa = (const float*)d_in[0];
    const float* lnw = (const float*)d_in[1];
    const float* lnb = (const float*)d_in[2];
    const float* wq  = (const float*)d_in[3];
    const float* wk  = (const float*)d_in[4];
    const float* wv  = (const float*)d_in[5];
    const float* wg  = (const float*)d_in[6];
    const float* bg  = (const float*)d_in[7];
    const float* wo  = (const float*)d_in[8];
    const float* bo  = (const float*)d_in[9];
    float* out = (float*)d_out;

    const int smem_bytes = (int)sizeof(Smem);
    cudaFuncSetAttribute(msa_col_attn_v5,
                         cudaFuncAttributeMaxDynamicSharedMemorySize, smem_bytes);
    msa_col_attn_v5<<<LRES, NT, smem_bytes>>>(
        msa, lnw, lnb, wq, wk, wv, wg, bg, wo, bo, out);
}